// round 5
// baseline (speedup 1.0000x reference)
#include <cuda_runtime.h>

#define TOTAL_QUBITS 24
#define DIM (1u << TOTAL_QUBITS)
#define BATCH 4
#define GROUPS_TOTAL (BATCH * (DIM >> 4))   // 4 * 2^20 float4-groups

#define NUM_SMS 148
#define CTAS_PER_SM 8
#define BLOCK_THREADS 256

// 2-qubit gate on batched 2^24 statevector. Pure streaming: 256MB read +
// 256MB write, zero reuse. Persistent single-wave grid-stride kernel:
// 148*8 CTAs resident, each thread loops over ~14 float4-groups, keeping
// the memory pipeline continuously full (no wave transitions, no per-CTA
// ramp-up/drain). 128-bit LD/ST on all 8 streams.
__global__ __launch_bounds__(BLOCK_THREADS, CTAS_PER_SM)
void quantum_gate_kernel(const float* __restrict__ state,
                         const float* __restrict__ matrix,
                         const int* __restrict__ q0p,
                         const int* __restrict__ q1p,
                         float* __restrict__ out)
{
    const int q0 = q0p[0];
    const int q1 = q1p[0];
    const int bq0 = TOTAL_QUBITS - 1 - q0;   // linear-index bit = HIGH bit of g
    const int bq1 = TOTAL_QUBITS - 1 - q1;   // linear-index bit = LOW  bit of g
    const int blo = bq0 < bq1 ? bq0 : bq1;
    const int bhi = bq0 < bq1 ? bq1 : bq0;

    float m[16];
#pragma unroll
    for (int i = 0; i < 16; i++) m[i] = __ldg(matrix + i);

    const unsigned off1 = 1u << bq1;                       // toggles low bit of g
    const unsigned off2 = 1u << bq0;                       // toggles high bit of g
    const unsigned stride = gridDim.x * blockDim.x;
    const unsigned t0 = blockIdx.x * blockDim.x + threadIdx.x;

    if (blo >= 2) {
        // ---- vectorized path (actual case: gate bits 13 and 20) ----
        for (unsigned t = t0; t < GROUPS_TOTAL; t += stride) {
            unsigned b  = t >> 20;                         // batch
            unsigned rv = t & ((1u << 20) - 1);
            unsigned r    = rv << 2;                       // rest index (mult of 4)
            unsigned low  = r & ((1u << blo) - 1);
            unsigned mid  = (r >> blo) & ((1u << (bhi - 1 - blo)) - 1);
            unsigned high = r >> (bhi - 1);
            unsigned base = low | (mid << (blo + 1)) | (high << (bhi + 1));

            const float* sp = state + ((size_t)b << TOTAL_QUBITS);
            float*       op = out   + ((size_t)b << TOTAL_QUBITS);

            float4 s0 = *reinterpret_cast<const float4*>(sp + base);
            float4 s1 = *reinterpret_cast<const float4*>(sp + base + off1);
            float4 s2 = *reinterpret_cast<const float4*>(sp + base + off2);
            float4 s3 = *reinterpret_cast<const float4*>(sp + base + off1 + off2);

            float4 o0, o1, o2, o3;
#define APPLY(comp)                                                              \
            o0.comp = m[0]*s0.comp + m[1]*s1.comp + m[2]*s2.comp + m[3]*s3.comp; \
            o1.comp = m[4]*s0.comp + m[5]*s1.comp + m[6]*s2.comp + m[7]*s3.comp; \
            o2.comp = m[8]*s0.comp + m[9]*s1.comp + m[10]*s2.comp + m[11]*s3.comp; \
            o3.comp = m[12]*s0.comp + m[13]*s1.comp + m[14]*s2.comp + m[15]*s3.comp;
            APPLY(x) APPLY(y) APPLY(z) APPLY(w)
#undef APPLY

            *reinterpret_cast<float4*>(op + base)               = o0;
            *reinterpret_cast<float4*>(op + base + off1)        = o1;
            *reinterpret_cast<float4*>(op + base + off2)        = o2;
            *reinterpret_cast<float4*>(op + base + off1 + off2) = o3;
        }
    } else {
        // ---- scalar fallback (gate bit in low 2 index bits) ----
        for (unsigned t = t0; t < GROUPS_TOTAL; t += stride) {
            unsigned b  = t >> 20;
            unsigned rv = t & ((1u << 20) - 1);
            const float* sp = state + ((size_t)b << TOTAL_QUBITS);
            float*       op = out   + ((size_t)b << TOTAL_QUBITS);
#pragma unroll
            for (int i = 0; i < 4; i++) {
                unsigned r    = (rv << 2) + i;
                unsigned low  = r & ((1u << blo) - 1);
                unsigned midmask = (bhi - 1 - blo) >= 32 ? 0xFFFFFFFFu
                                                         : ((1u << (bhi - 1 - blo)) - 1);
                unsigned mid  = (r >> blo) & midmask;
                unsigned high = r >> (bhi - 1);
                unsigned base = low | (mid << (blo + 1)) | (high << (bhi + 1));

                float s0 = sp[base];
                float s1 = sp[base + off1];
                float s2 = sp[base + off2];
                float s3 = sp[base + off1 + off2];

                op[base]               = m[0]*s0  + m[1]*s1  + m[2]*s2  + m[3]*s3;
                op[base + off1]        = m[4]*s0  + m[5]*s1  + m[6]*s2  + m[7]*s3;
                op[base + off2]        = m[8]*s0  + m[9]*s1  + m[10]*s2 + m[11]*s3;
                op[base + off1 + off2] = m[12]*s0 + m[13]*s1 + m[14]*s2 + m[15]*s3;
            }
        }
    }
}

extern "C" void kernel_launch(void* const* d_in, const int* in_sizes, int n_in,
                              void* d_out, int out_size)
{
    const float* state  = (const float*)d_in[0];
    const float* matrix = (const float*)d_in[1];
    const int*   q0     = (const int*)d_in[2];
    const int*   q1     = (const int*)d_in[3];
    float*       out    = (float*)d_out;

    const unsigned grid = NUM_SMS * CTAS_PER_SM;           // 1184 CTAs, single wave
    quantum_gate_kernel<<<grid, BLOCK_THREADS>>>(state, matrix, q0, q1, out);
}

// round 6
// speedup vs baseline: 1.1403x; 1.1403x over previous
#include <cuda_runtime.h>

#define TOTAL_QUBITS 24
#define DIM (1u << TOTAL_QUBITS)
#define BATCH 4

// 2-qubit gate on batched 2^24 statevector. Pure streaming: 256MB read +
// 256MB write, zero reuse -> memory-bound at the mixed-stream HBM ceiling
// (~6.37 TB/s, 80% of spec — confirmed across 5 kernel variants).
// Best shape: one float4-group (4 consecutive rest indices) per thread,
// 32 regs / high occupancy, one-shot CTAs (scheduler churn overlaps load
// ramp with store drain), 128-bit LD/ST on all 8 streams, evict-first hints.
__global__ __launch_bounds__(256)
void quantum_gate_kernel(const float* __restrict__ state,
                         const float* __restrict__ matrix,
                         const int* __restrict__ q0p,
                         const int* __restrict__ q1p,
                         float* __restrict__ out)
{
    const int q0 = q0p[0];
    const int q1 = q1p[0];
    const int bq0 = TOTAL_QUBITS - 1 - q0;   // linear-index bit = HIGH bit of g
    const int bq1 = TOTAL_QUBITS - 1 - q1;   // linear-index bit = LOW  bit of g
    const int blo = bq0 < bq1 ? bq0 : bq1;
    const int bhi = bq0 < bq1 ? bq1 : bq0;

    float m[16];
#pragma unroll
    for (int i = 0; i < 16; i++) m[i] = __ldg(matrix + i);

    const unsigned vec_per_batch = DIM >> 4;               // 2^20 groups per batch
    unsigned t = blockIdx.x * blockDim.x + threadIdx.x;
    unsigned b  = t >> 20;
    unsigned rv = t & (vec_per_batch - 1);
    if (b >= BATCH) return;

    const size_t boff = (size_t)b << TOTAL_QUBITS;
    const unsigned off1 = 1u << bq1;                       // toggles low bit of g
    const unsigned off2 = 1u << bq0;                       // toggles high bit of g

    if (blo >= 2) {
        // ---- vectorized path (actual case: gate bits 13 and 20) ----
        unsigned r    = rv << 2;
        unsigned low  = r & ((1u << blo) - 1);
        unsigned mid  = (r >> blo) & ((1u << (bhi - 1 - blo)) - 1);
        unsigned high = r >> (bhi - 1);
        unsigned base = low | (mid << (blo + 1)) | (high << (bhi + 1));

        const float* sp = state + boff;
        float*       op = out   + boff;

        float4 s0 = __ldcs(reinterpret_cast<const float4*>(sp + base));
        float4 s1 = __ldcs(reinterpret_cast<const float4*>(sp + base + off1));
        float4 s2 = __ldcs(reinterpret_cast<const float4*>(sp + base + off2));
        float4 s3 = __ldcs(reinterpret_cast<const float4*>(sp + base + off1 + off2));

        float4 o0, o1, o2, o3;
#define APPLY(comp)                                                              \
        o0.comp = m[0]*s0.comp + m[1]*s1.comp + m[2]*s2.comp + m[3]*s3.comp;     \
        o1.comp = m[4]*s0.comp + m[5]*s1.comp + m[6]*s2.comp + m[7]*s3.comp;     \
        o2.comp = m[8]*s0.comp + m[9]*s1.comp + m[10]*s2.comp + m[11]*s3.comp;   \
        o3.comp = m[12]*s0.comp + m[13]*s1.comp + m[14]*s2.comp + m[15]*s3.comp;
        APPLY(x) APPLY(y) APPLY(z) APPLY(w)
#undef APPLY

        __stcs(reinterpret_cast<float4*>(op + base),               o0);
        __stcs(reinterpret_cast<float4*>(op + base + off1),        o1);
        __stcs(reinterpret_cast<float4*>(op + base + off2),        o2);
        __stcs(reinterpret_cast<float4*>(op + base + off1 + off2), o3);
    } else {
        // ---- scalar fallback (gate bit in low 2 index bits) ----
        const float* sp = state + boff;
        float*       op = out   + boff;
#pragma unroll
        for (int i = 0; i < 4; i++) {
            unsigned r    = (rv << 2) + i;
            unsigned low  = r & ((1u << blo) - 1);
            unsigned midmask = (bhi - 1 - blo) >= 32 ? 0xFFFFFFFFu
                                                     : ((1u << (bhi - 1 - blo)) - 1);
            unsigned mid  = (r >> blo) & midmask;
            unsigned high = r >> (bhi - 1);
            unsigned base = low | (mid << (blo + 1)) | (high << (bhi + 1));

            float s0 = sp[base];
            float s1 = sp[base + off1];
            float s2 = sp[base + off2];
            float s3 = sp[base + off1 + off2];

            op[base]               = m[0]*s0  + m[1]*s1  + m[2]*s2  + m[3]*s3;
            op[base + off1]        = m[4]*s0  + m[5]*s1  + m[6]*s2  + m[7]*s3;
            op[base + off2]        = m[8]*s0  + m[9]*s1  + m[10]*s2 + m[11]*s3;
            op[base + off1 + off2] = m[12]*s0 + m[13]*s1 + m[14]*s2 + m[15]*s3;
        }
    }
}

extern "C" void kernel_launch(void* const* d_in, const int* in_sizes, int n_in,
                              void* d_out, int out_size)
{
    const float* state  = (const float*)d_in[0];
    const float* matrix = (const float*)d_in[1];
    const int*   q0     = (const int*)d_in[2];
    const int*   q1     = (const int*)d_in[3];
    float*       out    = (float*)d_out;

    const unsigned total_threads = BATCH * (DIM >> 4);     // 2^22
    const unsigned block = 256;
    const unsigned grid  = (total_threads + block - 1) / block;   // 16384
    quantum_gate_kernel<<<grid, block>>>(state, matrix, q0, q1, out);
}